// round 8
// baseline (speedup 1.0000x reference)
#include <cuda_runtime.h>
#include <cuda_bf16.h>
#include <cstdint>

// Problem constants
#define BB   2
#define NN   10000
#define EE   100000
#define FF   512
#define HH   512
#define MROWS (BB*NN)        // 20000 rows into the node GEMM
#define NTOT  (2*HH)         // 1024 cols: [W1 | W2]
#define NEDGE (BB*EE)        // 200000 directed edge slots
#define NSEG  (BB*NN)        // 20000 segments per direction

// ---------------- scratch (static device globals; no allocation) -------------
__device__ __nv_bfloat16  g_preb[(size_t)MROWS * NTOT];    // 41 MB: X@[W1|W2] bf16
__device__ __nv_bfloat16  g_Xb [(size_t)MROWS * FF];       // 20.5 MB bf16 X
__device__ __nv_bfloat16  g_Wb [(size_t)NTOT  * FF];       // 1 MB: [W1|W2]^T K-major
__device__ __nv_bfloat16  g_A  [(size_t)MROWS * NTOT];     // 41 MB: [A1|A2] per node
__device__ float          g_eij[NEDGE];
__device__ float          g_eji[NEDGE];
__device__ float          g_sums[2 * NSEG];                // [src sums | dst sums]

// ======================= PTX helpers (non-'a' safe) ===========================
__device__ __forceinline__ uint32_t smem_to_u32(const void* smem_ptr) {
    uint32_t addr;
    asm("{ .reg .u64 tmp; cvta.to.shared.u64 tmp, %1; cvt.u32.u64 %0, tmp; }"
        : "=r"(addr) : "l"(smem_ptr));
    return addr;
}

__device__ __forceinline__ void cp_async16(uint32_t dst, const void* src, int src_bytes) {
    asm volatile("cp.async.cg.shared.global [%0], [%1], 16, %2;"
        :: "r"(dst), "l"(src), "r"(src_bytes) : "memory");
}
#define CP_COMMIT() asm volatile("cp.async.commit_group;" ::: "memory")
#define CP_WAIT(n)  asm volatile("cp.async.wait_group %0;" :: "n"(n) : "memory")

__device__ __forceinline__ void ldmatrix_x4(
    uint32_t& r0, uint32_t& r1, uint32_t& r2, uint32_t& r3, uint32_t addr)
{
    asm volatile("ldmatrix.sync.aligned.m8n8.x4.shared.b16 {%0,%1,%2,%3}, [%4];"
        : "=r"(r0), "=r"(r1), "=r"(r2), "=r"(r3) : "r"(addr));
}

__device__ __forceinline__ void mma_bf16(
    float* c, uint32_t a0, uint32_t a1, uint32_t a2, uint32_t a3,
    uint32_t b0, uint32_t b1)
{
    asm volatile(
        "mma.sync.aligned.m16n8k16.row.col.f32.bf16.bf16.f32 "
        "{%0,%1,%2,%3}, {%4,%5,%6,%7}, {%8,%9}, {%0,%1,%2,%3};"
        : "+f"(c[0]), "+f"(c[1]), "+f"(c[2]), "+f"(c[3])
        : "r"(a0), "r"(a1), "r"(a2), "r"(a3), "r"(b0), "r"(b1));
}

// Packed fp32x2 FMA (Blackwell FFMA2 — only reachable via PTX f32x2)
__device__ __forceinline__ void fma_f32x2(
    unsigned long long& d, unsigned long long a, unsigned long long b,
    unsigned long long c)
{
    asm("fma.rn.f32x2 %0, %1, %2, %3;" : "=l"(d) : "l"(a), "l"(b), "l"(c));
}
__device__ __forceinline__ unsigned long long pack_f2(float lo, float hi) {
    unsigned long long r;
    asm("mov.b64 %0, {%1, %2};" : "=l"(r) : "f"(lo), "f"(hi));
    return r;
}
__device__ __forceinline__ float2 unpack_f2(unsigned long long v) {
    float lo, hi;
    asm("mov.b64 {%0, %1}, %2;" : "=f"(lo), "=f"(hi) : "l"(v));
    return make_float2(lo, hi);
}

// ---------------- kernel 0: zero segment sums --------------------------------
__global__ void zero_sums_kernel() {
    int i = blockIdx.x * blockDim.x + threadIdx.x;
    if (i < 2 * NSEG) g_sums[i] = 0.0f;
}

// ---------------- kernel A: convert X -> bf16 ---------------------------------
__global__ __launch_bounds__(256) void convX_kernel(const float* __restrict__ X) {
    size_t i = ((size_t)blockIdx.x * 256 + threadIdx.x) * 8;
    if (i >= (size_t)MROWS * FF) return;
    float4 a = *(const float4*)(X + i);
    float4 b = *(const float4*)(X + i + 4);
    __nv_bfloat162 o0 = __float22bfloat162_rn(make_float2(a.x, a.y));
    __nv_bfloat162 o1 = __float22bfloat162_rn(make_float2(a.z, a.w));
    __nv_bfloat162 o2 = __float22bfloat162_rn(make_float2(b.x, b.y));
    __nv_bfloat162 o3 = __float22bfloat162_rn(make_float2(b.z, b.w));
    uint4 o;
    o.x = *(uint32_t*)&o0; o.y = *(uint32_t*)&o1;
    o.z = *(uint32_t*)&o2; o.w = *(uint32_t*)&o3;
    *(uint4*)(g_Xb + i) = o;
}

// ---------------- kernel B: transpose [W1|W2] -> g_Wb[n][k] bf16 --------------
__global__ __launch_bounds__(256) void transW_kernel(
    const float* __restrict__ W1, const float* __restrict__ W2)
{
    __shared__ float t[32][33];
    int k0  = blockIdx.x * 32;
    int n0g = blockIdx.y * 32;
    const float* W = (n0g < HH) ? W1 : W2;
    int n0 = n0g & (HH - 1);
    int tx = threadIdx.x, ty = threadIdx.y;  // (32, 8)
#pragma unroll
    for (int j = 0; j < 4; j++)
        t[ty + 8 * j][tx] = W[(size_t)(k0 + ty + 8 * j) * HH + n0 + tx];
    __syncthreads();
#pragma unroll
    for (int j = 0; j < 4; j++)
        g_Wb[(size_t)(n0g + ty + 8 * j) * FF + k0 + tx] =
            __float2bfloat16(t[tx][ty + 8 * j]);
}

// ---------------- kernel 1: bf16 HMMA GEMM (mma.sync m16n8k16) ----------------
#define BK    64
#define LDS_  ((BK) + 8)          // 72 bf16 per smem row (144B)
#define NSTG  3
#define TILE_BYTES   (128 * LDS_ * 2)
#define STAGE_BYTES  (2 * TILE_BYTES)
#define GEMM_SMEM    (NSTG * STAGE_BYTES)

__global__ __launch_bounds__(256) void gemm_mma_kernel()
{
    extern __shared__ __align__(16) char smem_raw[];
    const uint32_t sbase = smem_to_u32(smem_raw);

    const int tid  = threadIdx.x;
    const int wid  = tid >> 5;
    const int lane = tid & 31;

    const int m0 = blockIdx.y * 128;
    const int n0 = blockIdx.x * 128;

    const int warp_m = wid >> 1;
    const int warp_n = wid & 1;

    float acc[2][8][4];
#pragma unroll
    for (int i = 0; i < 2; i++)
#pragma unroll
        for (int j = 0; j < 8; j++)
#pragma unroll
            for (int q = 0; q < 4; q++) acc[i][j][q] = 0.0f;

    auto stageA = [&](int s) { return sbase + (uint32_t)s * STAGE_BYTES; };
    auto stageB = [&](int s) { return sbase + (uint32_t)s * STAGE_BYTES + TILE_BYTES; };

    auto load_tiles = [&](int it, int s) {
        int k0 = it * BK;
        uint32_t aA = stageA(s), aB = stageB(s);
#pragma unroll
        for (int j = 0; j < 4; j++) {
            int c   = tid + j * 256;
            int row = c >> 3;
            int sl  = c & 7;
            int gm  = m0 + row;
            uint32_t off = (uint32_t)(row * LDS_ + sl * 8) * 2;
            cp_async16(aA + off, g_Xb + (size_t)gm * FF + k0 + sl * 8,
                       (gm < MROWS) ? 16 : 0);
            cp_async16(aB + off, g_Wb + (size_t)(n0 + row) * FF + k0 + sl * 8, 16);
        }
        CP_COMMIT();
    };

    const int NIT = FF / BK;   // 8
    load_tiles(0, 0);
    load_tiles(1, 1);

#pragma unroll 1
    for (int it = 0; it < NIT; ++it) {
        int s = it % NSTG;
        // Single barrier per iter: stage (it+2)%3 == stage (it-1)%3; this
        // barrier guarantees all warps finished computing iter it-1.
        __syncthreads();
        if (it + 2 < NIT) { load_tiles(it + 2, (it + 2) % NSTG); CP_WAIT(2); }
        else if (it + 1 < NIT) { CP_WAIT(1); }
        else { CP_WAIT(0); }

        uint32_t aA = stageA(s), aB = stageB(s);
#pragma unroll
        for (int ks = 0; ks < BK; ks += 16) {
            uint32_t a[2][4];
#pragma unroll
            for (int tm = 0; tm < 2; tm++) {
                int r  = warp_m * 32 + tm * 16 + (lane & 15);
                int kk = ks + (lane >> 4) * 8;
                ldmatrix_x4(a[tm][0], a[tm][1], a[tm][2], a[tm][3],
                            aA + (uint32_t)(r * LDS_ + kk) * 2);
            }
            uint32_t b[8][2];
#pragma unroll
            for (int tp = 0; tp < 4; tp++) {
                int nrow = warp_n * 64 + tp * 16 + ((lane >> 4) * 8) + (lane & 7);
                int kk   = ks + (((lane >> 3) & 1) * 8);
                ldmatrix_x4(b[2*tp][0], b[2*tp][1], b[2*tp+1][0], b[2*tp+1][1],
                            aB + (uint32_t)(nrow * LDS_ + kk) * 2);
            }
#pragma unroll
            for (int tm = 0; tm < 2; tm++)
#pragma unroll
                for (int tn = 0; tn < 8; tn++)
                    mma_bf16(acc[tm][tn], a[tm][0], a[tm][1], a[tm][2], a[tm][3],
                             b[tn][0], b[tn][1]);
        }
    }

    // Epilogue: write bf16 to g_preb
    const int qrow = lane >> 2;
    const int qcol = (lane & 3) * 2;
#pragma unroll
    for (int tm = 0; tm < 2; tm++) {
        int mb = m0 + warp_m * 32 + tm * 16;
#pragma unroll
        for (int tn = 0; tn < 8; tn++) {
            int gcol = n0 + warp_n * 64 + tn * 8 + qcol;
            int r0 = mb + qrow;
            int r1 = mb + qrow + 8;
            __nv_bfloat162 p0 = __float22bfloat162_rn(
                make_float2(acc[tm][tn][0], acc[tm][tn][1]));
            __nv_bfloat162 p1 = __float22bfloat162_rn(
                make_float2(acc[tm][tn][2], acc[tm][tn][3]));
            if (r0 < MROWS)
                *(__nv_bfloat162*)(g_preb + (size_t)r0 * NTOT + gcol) = p0;
            if (r1 < MROWS)
                *(__nv_bfloat162*)(g_preb + (size_t)r1 * NTOT + gcol) = p1;
        }
    }
}

// ---------------- kernel 2: LayerNorm per row-half, bf16 in/out --------------
// Output interleaved per node: g_A[row][0:512) = A1, g_A[row][512:1024) = A2.
__global__ __launch_bounds__(256) void ln_kernel(
    const float* __restrict__ b1, const float* __restrict__ g1, const float* __restrict__ bb1,
    const float* __restrict__ b2, const float* __restrict__ g2, const float* __restrict__ bb2)
{
    int row  = blockIdx.x;
    int half = blockIdx.y;
    const __nv_bfloat16* p = g_preb + (size_t)row * NTOT + half * HH;
    const float* bv  = half ? b2  : b1;
    const float* gv  = half ? g2  : g1;
    const float* bbv = half ? bb2 : bb1;

    int t = threadIdx.x;
    float2 raw = __bfloat1622float2(*(const __nv_bfloat162*)(p + 2 * t));
    float2 bb2v = *(const float2*)(bv + 2 * t);
    float v0 = raw.x + bb2v.x;
    float v1 = raw.y + bb2v.y;

    float s  = v0 + v1;
    float sq = v0 * v0 + v1 * v1;
#pragma unroll
    for (int o = 16; o; o >>= 1) {
        s  += __shfl_xor_sync(0xffffffffu, s,  o);
        sq += __shfl_xor_sync(0xffffffffu, sq, o);
    }
    __shared__ float red[2][8];
    int w = t >> 5, l = t & 31;
    if (l == 0) { red[0][w] = s; red[1][w] = sq; }
    __syncthreads();
    float S = 0.f, SQ = 0.f;
#pragma unroll
    for (int i = 0; i < 8; i++) { S += red[0][i]; SQ += red[1][i]; }

    float mu  = S * (1.0f / HH);
    float var = SQ * (1.0f / HH) - mu * mu;
    float rs  = rsqrtf(var + 1e-5f);

    float2 gvv  = *(const float2*)(gv + 2 * t);
    float2 bbvv = *(const float2*)(bbv + 2 * t);
    __nv_bfloat16* Aout = g_A + (size_t)row * NTOT + half * HH;
    float o0 = (v0 - mu) * rs * gvv.x + bbvv.x;
    float o1 = (v1 - mu) * rs * gvv.y + bbvv.y;
    *(__nv_bfloat162*)(Aout + 2 * t) = __float22bfloat162_rn(make_float2(o0, o1));
}

// ---------------- kernel 3: warp-per-edge scoring (bf16 SIMD + FFMA2) --------
__global__ __launch_bounds__(256) void edge_kernel(
    const int* __restrict__ ei,
    const float* __restrict__ W3,
    const float* __restrict__ W4,
    const float* __restrict__ b4)
{
    int gw   = (blockIdx.x * 256 + threadIdx.x) >> 5;
    int lane = threadIdx.x & 31;
    if (gw >= NEDGE) return;
    int b = gw / EE;
    int e = gw - b * EE;

    int src = ei[(size_t)b * 2 * EE + e];
    int dst = ei[(size_t)b * 2 * EE + EE + e];

    // Each node row: [A1(512) | A2(512)] bf16, contiguous 2 KB.
    const __nv_bfloat16* ps = g_A + ((size_t)b * NN + src) * NTOT;
    const __nv_bfloat16* pd = g_A + ((size_t)b * NN + dst) * NTOT;
    const int eo = lane * 16;     // 16 elems per lane per half

    // Load as bf16x2 packets (8 per 16-elem slice)
    uint4 v1s0 = *(const uint4*)(ps + eo);
    uint4 v1s1 = *(const uint4*)(ps + eo + 8);
    uint4 v2s0 = *(const uint4*)(ps + HH + eo);
    uint4 v2s1 = *(const uint4*)(ps + HH + eo + 8);
    uint4 v1d0 = *(const uint4*)(pd + eo);
    uint4 v1d1 = *(const uint4*)(pd + eo + 8);
    uint4 v2d0 = *(const uint4*)(pd + HH + eo);
    uint4 v2d1 = *(const uint4*)(pd + HH + eo + 8);

    const __nv_bfloat162* u1s = (const __nv_bfloat162*)&v1s0;  // [0..3] then v1s1
    const __nv_bfloat162* u2s = (const __nv_bfloat162*)&v2s0;
    const __nv_bfloat162* u1d = (const __nv_bfloat162*)&v1d0;
    const __nv_bfloat162* u2d = (const __nv_bfloat162*)&v2d0;
    const __nv_bfloat162* u1sb = (const __nv_bfloat162*)&v1s1;
    const __nv_bfloat162* u2sb = (const __nv_bfloat162*)&v2s1;
    const __nv_bfloat162* u1db = (const __nv_bfloat162*)&v1d1;
    const __nv_bfloat162* u2db = (const __nv_bfloat162*)&v2d1;

    const __nv_bfloat162 z2 = __float2bfloat162_rn(0.0f);
    unsigned long long acc1 = pack_f2(0.f, 0.f);
    unsigned long long acc2 = pack_f2(0.f, 0.f);

#pragma unroll
    for (int j = 0; j < 8; j++) {
        __nv_bfloat162 x1s = (j < 4) ? u1s[j] : u1sb[j - 4];
        __nv_bfloat162 x2s = (j < 4) ? u2s[j] : u2sb[j - 4];
        __nv_bfloat162 x1d = (j < 4) ? u1d[j] : u1db[j - 4];
        __nv_bfloat162 x2d = (j < 4) ? u2d[j] : u2db[j - 4];

        __nv_bfloat162 h1 = __hmax2(__hadd2(x1s, x2d), z2);  // relu(a1i+a2j)
        __nv_bfloat162 h2 = __hmax2(__hadd2(x1d, x2s), z2);  // relu(a1j+a2i)

        float2 f1 = __bfloat1622float2(h1);
        float2 f2 = __bfloat1622float2(h2);
        float2 wv = *(const float2*)(W3 + eo + 2 * j);
        unsigned long long wp = pack_f2(wv.x, wv.y);

        fma_f32x2(acc1, pack_f2(f1.x, f1.y), wp, acc1);
        fma_f32x2(acc2, pack_f2(f2.x, f2.y), wp, acc2);
    }

    float2 a1f = unpack_f2(acc1);
    float2 a2f = unpack_f2(acc2);
    float s1 = a1f.x + a1f.y;
    float s2 = a2f.x + a2f.y;
#pragma unroll
    for (int o = 16; o; o >>= 1) {
        s1 += __shfl_xor_sync(0xffffffffu, s1, o);
        s2 += __shfl_xor_sync(0xffffffffu, s2, o);
    }
    if (lane == 0) {
        float d  = s1 - s2;                 // b3 cancels in Zij - Zji
        float w4 = W4[0], bb = b4[0];
        float vij = fmaxf(fmaf( d, w4, bb), 0.f);
        float vji = fmaxf(fmaf(-d, w4, bb), 0.f);
        float pi = expf(vij);               // max-subtraction removable: exact ratio
        float pj = expf(vji);
        g_eij[(size_t)b * EE + e] = pi;
        g_eji[(size_t)b * EE + e] = pj;
        atomicAdd(&g_sums[b * NN + src], pi);
        atomicAdd(&g_sums[NSEG + b * NN + dst], pj);
    }
}

// ---------------- kernel 4: normalize + write output -------------------------
__global__ __launch_bounds__(256) void norm_kernel(
    const int* __restrict__ ei,
    float* __restrict__ out)
{
    int i = blockIdx.x * 256 + threadIdx.x;
    if (i >= NEDGE) return;
    int b = i / EE;
    int e = i - b * EE;
    int src = ei[(size_t)b * 2 * EE + e];
    int dst = ei[(size_t)b * 2 * EE + EE + e];
    out[i]         = g_eij[i] / g_sums[b * NN + src];
    out[NEDGE + i] = g_eji[i] / g_sums[NSEG + b * NN + dst];
}

// ---------------- launcher ---------------------------------------------------
extern "C" void kernel_launch(void* const* d_in, const int* in_sizes, int n_in,
                              void* d_out, int out_size)
{
    int idx = 0;
    const float* X  = (const float*)d_in[idx++];   // node_features
    const int*   EI = (const int*)  d_in[idx++];   // edge_index
    if (idx < n_in && in_sizes[idx] == 1) idx++;   // num_nodes scalar (if present)
    const float* W1  = (const float*)d_in[idx++];
    const float* b1  = (const float*)d_in[idx++];
    const float* g1  = (const float*)d_in[idx++];
    const float* bb1 = (const float*)d_in[idx++];
    const float* W2  = (const float*)d_in[idx++];
    const float* b2  = (const float*)d_in[idx++];
    const float* g2  = (const float*)d_in[idx++];
    const float* bb2 = (const float*)d_in[idx++];
    const float* W3  = (const float*)d_in[idx++];
    idx++;                                          // b3 (cancels)
    const float* W4  = (const float*)d_in[idx++];
    const float* b4  = (const float*)d_in[idx++];

    float* out = (float*)d_out;

    zero_sums_kernel<<<(2 * NSEG + 255) / 256, 256>>>();

    convX_kernel<<<(int)(((size_t)MROWS * FF / 8 + 255) / 256), 256>>>(X);

    dim3 tgrid(FF / 32, NTOT / 32);
    transW_kernel<<<tgrid, dim3(32, 8)>>>(W1, W2);

    cudaFuncSetAttribute(gemm_mma_kernel,
                         cudaFuncAttributeMaxDynamicSharedMemorySize, GEMM_SMEM);
    dim3 ggrid(NTOT / 128, (MROWS + 127) / 128);
    gemm_mma_kernel<<<ggrid, 256, GEMM_SMEM>>>();

    dim3 lgrid(MROWS, 2);
    ln_kernel<<<lgrid, 256>>>(b1, g1, bb1, b2, g2, bb2);

    int edge_blocks = (NEDGE * 32 + 255) / 256;
    edge_kernel<<<edge_blocks, 256>>>(EI, W3, W4, b4);

    norm_kernel<<<(NEDGE + 255) / 256, 256>>>(EI, out);
}

// round 9
// speedup vs baseline: 1.2659x; 1.2659x over previous
#include <cuda_runtime.h>
#include <cuda_bf16.h>
#include <cstdint>

// Problem constants
#define BB   2
#define NN   10000
#define EE   100000
#define FF   512
#define HH   512
#define MROWS (BB*NN)        // 20000 rows into the node GEMM
#define NTOT  (2*HH)         // 1024 cols: [W1 | W2]
#define NEDGE (BB*EE)        // 200000 directed edge slots
#define NSEG  (BB*NN)        // 20000 segments per direction

// ---------------- scratch (static device globals; no allocation) -------------
__device__ __nv_bfloat16  g_preb[(size_t)MROWS * NTOT];    // 41 MB: X@[W1|W2] bf16
__device__ __nv_bfloat16  g_Xb [(size_t)MROWS * FF];       // 20.5 MB bf16 X
__device__ __nv_bfloat16  g_Wb [(size_t)NTOT  * FF];       // 1 MB: [W1|W2]^T K-major
__device__ __nv_bfloat16  g_A1[(size_t)MROWS * HH];        // 20.5 MB
__device__ __nv_bfloat16  g_A2[(size_t)MROWS * HH];        // 20.5 MB
__device__ float          g_eij[NEDGE];
__device__ float          g_eji[NEDGE];
__device__ float          g_sums[2 * NSEG];                // [src sums | dst sums]

// ======================= PTX helpers (non-'a' safe) ===========================
__device__ __forceinline__ uint32_t smem_to_u32(const void* smem_ptr) {
    uint32_t addr;
    asm("{ .reg .u64 tmp; cvta.to.shared.u64 tmp, %1; cvt.u32.u64 %0, tmp; }"
        : "=r"(addr) : "l"(smem_ptr));
    return addr;
}

__device__ __forceinline__ void cp_async16(uint32_t dst, const void* src, int src_bytes) {
    asm volatile("cp.async.cg.shared.global [%0], [%1], 16, %2;"
        :: "r"(dst), "l"(src), "r"(src_bytes) : "memory");
}
#define CP_COMMIT() asm volatile("cp.async.commit_group;" ::: "memory")
#define CP_WAIT(n)  asm volatile("cp.async.wait_group %0;" :: "n"(n) : "memory")

__device__ __forceinline__ void ldmatrix_x4(
    uint32_t& r0, uint32_t& r1, uint32_t& r2, uint32_t& r3, uint32_t addr)
{
    asm volatile("ldmatrix.sync.aligned.m8n8.x4.shared.b16 {%0,%1,%2,%3}, [%4];"
        : "=r"(r0), "=r"(r1), "=r"(r2), "=r"(r3) : "r"(addr));
}

__device__ __forceinline__ void mma_bf16(
    float* c, uint32_t a0, uint32_t a1, uint32_t a2, uint32_t a3,
    uint32_t b0, uint32_t b1)
{
    asm volatile(
        "mma.sync.aligned.m16n8k16.row.col.f32.bf16.bf16.f32 "
        "{%0,%1,%2,%3}, {%4,%5,%6,%7}, {%8,%9}, {%0,%1,%2,%3};"
        : "+f"(c[0]), "+f"(c[1]), "+f"(c[2]), "+f"(c[3])
        : "r"(a0), "r"(a1), "r"(a2), "r"(a3), "r"(b0), "r"(b1));
}

__device__ __forceinline__ void bf8_to_f(uint4 u, float* f) {
    const __nv_bfloat162* p = (const __nv_bfloat162*)&u;
#pragma unroll
    for (int i = 0; i < 4; i++) {
        float2 t = __bfloat1622float2(p[i]);
        f[2 * i]     = t.x;
        f[2 * i + 1] = t.y;
    }
}

// ---------------- kernel 0: zero segment sums --------------------------------
__global__ void zero_sums_kernel() {
    int i = blockIdx.x * blockDim.x + threadIdx.x;
    if (i < 2 * NSEG) g_sums[i] = 0.0f;
}

// ---------------- kernel A: convert X -> bf16 ---------------------------------
__global__ __launch_bounds__(256) void convX_kernel(const float* __restrict__ X) {
    size_t i = ((size_t)blockIdx.x * 256 + threadIdx.x) * 8;
    if (i >= (size_t)MROWS * FF) return;
    float4 a = *(const float4*)(X + i);
    float4 b = *(const float4*)(X + i + 4);
    __nv_bfloat162 o0 = __float22bfloat162_rn(make_float2(a.x, a.y));
    __nv_bfloat162 o1 = __float22bfloat162_rn(make_float2(a.z, a.w));
    __nv_bfloat162 o2 = __float22bfloat162_rn(make_float2(b.x, b.y));
    __nv_bfloat162 o3 = __float22bfloat162_rn(make_float2(b.z, b.w));
    uint4 o;
    o.x = *(uint32_t*)&o0; o.y = *(uint32_t*)&o1;
    o.z = *(uint32_t*)&o2; o.w = *(uint32_t*)&o3;
    *(uint4*)(g_Xb + i) = o;
}

// ---------------- kernel B: transpose [W1|W2] -> g_Wb[n][k] bf16 --------------
__global__ __launch_bounds__(256) void transW_kernel(
    const float* __restrict__ W1, const float* __restrict__ W2)
{
    __shared__ float t[32][33];
    int k0  = blockIdx.x * 32;
    int n0g = blockIdx.y * 32;
    const float* W = (n0g < HH) ? W1 : W2;
    int n0 = n0g & (HH - 1);
    int tx = threadIdx.x, ty = threadIdx.y;  // (32, 8)
#pragma unroll
    for (int j = 0; j < 4; j++)
        t[ty + 8 * j][tx] = W[(size_t)(k0 + ty + 8 * j) * HH + n0 + tx];
    __syncthreads();
#pragma unroll
    for (int j = 0; j < 4; j++)
        g_Wb[(size_t)(n0g + ty + 8 * j) * FF + k0 + tx] =
            __float2bfloat16(t[tx][ty + 8 * j]);
}

// ---------------- kernel 1: bf16 HMMA GEMM (mma.sync m16n8k16) ----------------
// Parameterized by row base/limit so the two batches can pipeline on streams.
#define BK    64
#define LDS_  ((BK) + 8)          // 72 bf16 per smem row (144B)
#define NSTG  3
#define TILE_BYTES   (128 * LDS_ * 2)
#define STAGE_BYTES  (2 * TILE_BYTES)
#define GEMM_SMEM    (NSTG * STAGE_BYTES)

__global__ __launch_bounds__(256) void gemm_mma_kernel(int mbase, int mlim)
{
    extern __shared__ __align__(16) char smem_raw[];
    const uint32_t sbase = smem_to_u32(smem_raw);

    const int tid  = threadIdx.x;
    const int wid  = tid >> 5;
    const int lane = tid & 31;

    const int m0 = mbase + blockIdx.y * 128;
    const int n0 = blockIdx.x * 128;

    const int warp_m = wid >> 1;
    const int warp_n = wid & 1;

    float acc[2][8][4];
#pragma unroll
    for (int i = 0; i < 2; i++)
#pragma unroll
        for (int j = 0; j < 8; j++)
#pragma unroll
            for (int q = 0; q < 4; q++) acc[i][j][q] = 0.0f;

    auto stageA = [&](int s) { return sbase + (uint32_t)s * STAGE_BYTES; };
    auto stageB = [&](int s) { return sbase + (uint32_t)s * STAGE_BYTES + TILE_BYTES; };

    auto load_tiles = [&](int it, int s) {
        int k0 = it * BK;
        uint32_t aA = stageA(s), aB = stageB(s);
#pragma unroll
        for (int j = 0; j < 4; j++) {
            int c   = tid + j * 256;
            int row = c >> 3;
            int sl  = c & 7;
            int gm  = m0 + row;
            uint32_t off = (uint32_t)(row * LDS_ + sl * 8) * 2;
            cp_async16(aA + off, g_Xb + (size_t)gm * FF + k0 + sl * 8,
                       (gm < mlim) ? 16 : 0);
            cp_async16(aB + off, g_Wb + (size_t)(n0 + row) * FF + k0 + sl * 8, 16);
        }
        CP_COMMIT();
    };

    const int NIT = FF / BK;   // 8
    load_tiles(0, 0);
    load_tiles(1, 1);

#pragma unroll 1
    for (int it = 0; it < NIT; ++it) {
        int s = it % NSTG;
        // Single barrier per iter: stage (it+2)%3 == stage (it-1)%3; this
        // barrier guarantees all warps finished computing iter it-1.
        __syncthreads();
        if (it + 2 < NIT) { load_tiles(it + 2, (it + 2) % NSTG); CP_WAIT(2); }
        else if (it + 1 < NIT) { CP_WAIT(1); }
        else { CP_WAIT(0); }

        uint32_t aA = stageA(s), aB = stageB(s);
#pragma unroll
        for (int ks = 0; ks < BK; ks += 16) {
            uint32_t a[2][4];
#pragma unroll
            for (int tm = 0; tm < 2; tm++) {
                int r  = warp_m * 32 + tm * 16 + (lane & 15);
                int kk = ks + (lane >> 4) * 8;
                ldmatrix_x4(a[tm][0], a[tm][1], a[tm][2], a[tm][3],
                            aA + (uint32_t)(r * LDS_ + kk) * 2);
            }
            uint32_t b[8][2];
#pragma unroll
            for (int tp = 0; tp < 4; tp++) {
                int nrow = warp_n * 64 + tp * 16 + ((lane >> 4) * 8) + (lane & 7);
                int kk   = ks + (((lane >> 3) & 1) * 8);
                ldmatrix_x4(b[2*tp][0], b[2*tp][1], b[2*tp+1][0], b[2*tp+1][1],
                            aB + (uint32_t)(nrow * LDS_ + kk) * 2);
            }
#pragma unroll
            for (int tm = 0; tm < 2; tm++)
#pragma unroll
                for (int tn = 0; tn < 8; tn++)
                    mma_bf16(acc[tm][tn], a[tm][0], a[tm][1], a[tm][2], a[tm][3],
                             b[tn][0], b[tn][1]);
        }
    }

    // Epilogue: write bf16 to g_preb
    const int qrow = lane >> 2;
    const int qcol = (lane & 3) * 2;
#pragma unroll
    for (int tm = 0; tm < 2; tm++) {
        int mb = m0 + warp_m * 32 + tm * 16;
#pragma unroll
        for (int tn = 0; tn < 8; tn++) {
            int gcol = n0 + warp_n * 64 + tn * 8 + qcol;
            int r0 = mb + qrow;
            int r1 = mb + qrow + 8;
            __nv_bfloat162 p0 = __float22bfloat162_rn(
                make_float2(acc[tm][tn][0], acc[tm][tn][1]));
            __nv_bfloat162 p1 = __float22bfloat162_rn(
                make_float2(acc[tm][tn][2], acc[tm][tn][3]));
            if (r0 < mlim)
                *(__nv_bfloat162*)(g_preb + (size_t)r0 * NTOT + gcol) = p0;
            if (r1 < mlim)
                *(__nv_bfloat162*)(g_preb + (size_t)r1 * NTOT + gcol) = p1;
        }
    }
}

// ---------------- kernel 2: LayerNorm per row-half, bf16 in/out --------------
__global__ __launch_bounds__(256) void ln_kernel(
    int rbase,
    const float* __restrict__ b1, const float* __restrict__ g1, const float* __restrict__ bb1,
    const float* __restrict__ b2, const float* __restrict__ g2, const float* __restrict__ bb2)
{
    int row  = rbase + blockIdx.x;
    int half = blockIdx.y;
    const __nv_bfloat16* p = g_preb + (size_t)row * NTOT + half * HH;
    const float* bv  = half ? b2  : b1;
    const float* gv  = half ? g2  : g1;
    const float* bbv = half ? bb2 : bb1;

    int t = threadIdx.x;
    float2 raw = __bfloat1622float2(*(const __nv_bfloat162*)(p + 2 * t));
    float2 bb2v = *(const float2*)(bv + 2 * t);
    float v0 = raw.x + bb2v.x;
    float v1 = raw.y + bb2v.y;

    float s  = v0 + v1;
    float sq = v0 * v0 + v1 * v1;
#pragma unroll
    for (int o = 16; o; o >>= 1) {
        s  += __shfl_xor_sync(0xffffffffu, s,  o);
        sq += __shfl_xor_sync(0xffffffffu, sq, o);
    }
    __shared__ float red[2][8];
    int w = t >> 5, l = t & 31;
    if (l == 0) { red[0][w] = s; red[1][w] = sq; }
    __syncthreads();
    float S = 0.f, SQ = 0.f;
#pragma unroll
    for (int i = 0; i < 8; i++) { S += red[0][i]; SQ += red[1][i]; }

    float mu  = S * (1.0f / HH);
    float var = SQ * (1.0f / HH) - mu * mu;
    float rs  = rsqrtf(var + 1e-5f);

    float2 gvv  = *(const float2*)(gv + 2 * t);
    float2 bbvv = *(const float2*)(bbv + 2 * t);
    __nv_bfloat16* Aout = (half ? g_A2 : g_A1) + (size_t)row * HH;
    float o0 = (v0 - mu) * rs * gvv.x + bbvv.x;
    float o1 = (v1 - mu) * rs * gvv.y + bbvv.y;
    *(__nv_bfloat162*)(Aout + 2 * t) = __float22bfloat162_rn(make_float2(o0, o1));
}

// ---------------- kernel 3: warp-per-edge scoring + segment sums -------------
// One batch per launch (b fixed) so edge(b0) can overlap gemm(b1).
__global__ __launch_bounds__(256) void edge_kernel(
    int b,
    const int* __restrict__ ei,
    const float* __restrict__ W3,
    const float* __restrict__ W4,
    const float* __restrict__ b4)
{
    int e    = (blockIdx.x * 256 + threadIdx.x) >> 5;
    int lane = threadIdx.x & 31;
    if (e >= EE) return;

    int src = ei[(size_t)b * 2 * EE + e];
    int dst = ei[(size_t)b * 2 * EE + EE + e];

    const __nv_bfloat16* a1s = g_A1 + ((size_t)b * NN + src) * HH;
    const __nv_bfloat16* a2s = g_A2 + ((size_t)b * NN + src) * HH;
    const __nv_bfloat16* a1d = g_A1 + ((size_t)b * NN + dst) * HH;
    const __nv_bfloat16* a2d = g_A2 + ((size_t)b * NN + dst) * HH;

    float s1 = 0.f, s2 = 0.f;
#pragma unroll
    for (int i = 0; i < 2; i++) {
        int off = (i * 32 + lane) * 8;
        float x1s[8], x2s[8], x1d[8], x2d[8];
        bf8_to_f(*(const uint4*)(a1s + off), x1s);
        bf8_to_f(*(const uint4*)(a2d + off), x2d);
        bf8_to_f(*(const uint4*)(a1d + off), x1d);
        bf8_to_f(*(const uint4*)(a2s + off), x2s);
        float4 wa = *(const float4*)(W3 + off);
        float4 wb = *(const float4*)(W3 + off + 4);
        float w[8] = {wa.x, wa.y, wa.z, wa.w, wb.x, wb.y, wb.z, wb.w};
#pragma unroll
        for (int j = 0; j < 8; j++) {
            s1 = fmaf(fmaxf(x1s[j] + x2d[j], 0.f), w[j], s1);
            s2 = fmaf(fmaxf(x1d[j] + x2s[j], 0.f), w[j], s2);
        }
    }
#pragma unroll
    for (int o = 16; o; o >>= 1) {
        s1 += __shfl_xor_sync(0xffffffffu, s1, o);
        s2 += __shfl_xor_sync(0xffffffffu, s2, o);
    }
    if (lane == 0) {
        float d  = s1 - s2;                 // b3 cancels in Zij - Zji
        float w4 = W4[0], bb = b4[0];
        float vij = fmaxf(fmaf( d, w4, bb), 0.f);
        float vji = fmaxf(fmaf(-d, w4, bb), 0.f);
        float pi = expf(vij);               // max-subtraction removable: exact ratio
        float pj = expf(vji);
        g_eij[(size_t)b * EE + e] = pi;
        g_eji[(size_t)b * EE + e] = pj;
        atomicAdd(&g_sums[b * NN + src], pi);
        atomicAdd(&g_sums[NSEG + b * NN + dst], pj);
    }
}

// ---------------- kernel 4: normalize + write output -------------------------
__global__ __launch_bounds__(256) void norm_kernel(
    const int* __restrict__ ei,
    float* __restrict__ out)
{
    int i = blockIdx.x * 256 + threadIdx.x;
    if (i >= NEDGE) return;
    int b = i / EE;
    int e = i - b * EE;
    int src = ei[(size_t)b * 2 * EE + e];
    int dst = ei[(size_t)b * 2 * EE + EE + e];
    out[i]         = g_eij[i] / g_sums[b * NN + src];
    out[NEDGE + i] = g_eji[i] / g_sums[NSEG + b * NN + dst];
}

// ---------------- launcher ---------------------------------------------------
extern "C" void kernel_launch(void* const* d_in, const int* in_sizes, int n_in,
                              void* d_out, int out_size)
{
    int idx = 0;
    const float* X  = (const float*)d_in[idx++];   // node_features
    const int*   EI = (const int*)  d_in[idx++];   // edge_index
    if (idx < n_in && in_sizes[idx] == 1) idx++;   // num_nodes scalar (if present)
    const float* W1  = (const float*)d_in[idx++];
    const float* b1  = (const float*)d_in[idx++];
    const float* g1  = (const float*)d_in[idx++];
    const float* bb1 = (const float*)d_in[idx++];
    const float* W2  = (const float*)d_in[idx++];
    const float* b2  = (const float*)d_in[idx++];
    const float* g2  = (const float*)d_in[idx++];
    const float* bb2 = (const float*)d_in[idx++];
    const float* W3  = (const float*)d_in[idx++];
    idx++;                                          // b3 (cancels)
    const float* W4  = (const float*)d_in[idx++];
    const float* b4  = (const float*)d_in[idx++];

    float* out = (float*)d_out;

    cudaFuncSetAttribute(gemm_mma_kernel,
                         cudaFuncAttributeMaxDynamicSharedMemorySize, GEMM_SMEM);

    // Side stream + fork/join events (created per call, intentionally leaked:
    // kernel_launch is invoked only a handful of times; objects used by the
    // captured graph must outlive capture).
    cudaStream_t s2;
    cudaEvent_t evG0, evJoin;
    bool forked =
        (cudaStreamCreateWithFlags(&s2, cudaStreamNonBlocking) == cudaSuccess) &&
        (cudaEventCreateWithFlags(&evG0, cudaEventDisableTiming) == cudaSuccess) &&
        (cudaEventCreateWithFlags(&evJoin, cudaEventDisableTiming) == cudaSuccess);

    const int edge_blocks = (EE * 32 + 255) / 256;
    const dim3 ggrid(NTOT / 128, (NN + 127) / 128);   // per-batch GEMM grid
    const dim3 lgrid(NN, 2);
    const dim3 tgrid(FF / 32, NTOT / 32);

    // Prologue (stream 0)
    zero_sums_kernel<<<(2 * NSEG + 255) / 256, 256>>>();
    convX_kernel<<<(int)(((size_t)MROWS * FF / 8 + 255) / 256), 256>>>(X);
    transW_kernel<<<tgrid, dim3(32, 8)>>>(W1, W2);

    // GEMM batch 0 (stream 0)
    gemm_mma_kernel<<<ggrid, 256, GEMM_SMEM>>>(0, NN);

    if (forked) {
        // Fork: batch-1 chain on s2, staggered after GEMM(b0)
        cudaEventRecord(evG0, 0);
        cudaStreamWaitEvent(s2, evG0, 0);
        gemm_mma_kernel<<<ggrid, 256, GEMM_SMEM, s2>>>(NN, MROWS);
        ln_kernel<<<lgrid, 256, 0, s2>>>(NN, b1, g1, bb1, b2, g2, bb2);
        edge_kernel<<<edge_blocks, 256, 0, s2>>>(1, EI, W3, W4, b4);
        cudaEventRecord(evJoin, s2);

        // Batch-0 tail (stream 0) overlaps GEMM(b1)
        ln_kernel<<<lgrid, 256>>>(0, b1, g1, bb1, b2, g2, bb2);
        edge_kernel<<<edge_blocks, 256>>>(0, EI, W3, W4, b4);

        // Join + epilogue
        cudaStreamWaitEvent(0, evJoin, 0);
    } else {
        // Fallback: fully sequential (identical math)
        gemm_mma_kernel<<<ggrid, 256, GEMM_SMEM>>>(NN, MROWS);
        ln_kernel<<<lgrid, 256>>>(0, b1, g1, bb1, b2, g2, bb2);
        ln_kernel<<<lgrid, 256>>>(NN, b1, g1, bb1, b2, g2, bb2);
        edge_kernel<<<edge_blocks, 256>>>(0, EI, W3, W4, b4);
        edge_kernel<<<edge_blocks, 256>>>(1, EI, W3, W4, b4);
    }

    norm_kernel<<<(NEDGE + 255) / 256, 256>>>(EI, out);
}